// round 3
// baseline (speedup 1.0000x reference)
#include <cuda_runtime.h>

#define N_ATOMS 10000
#define N_PAIRS 500000
#define N_DESC  64
#define N_GROUPS (N_PAIRS / 2)          // 2 pairs per warp-iteration

#define PAIR_BLOCKS 1184                 // 148 SMs * 8 CTAs -> exactly one wave
#define PAIR_TPB    256

// Precomputed per-atom table: g[n,d] = (1 - tanh^2(coeffs*w1+b1)) * w1[d] * w_last[d]
__device__ float g_table[N_ATOMS * N_DESC];

// ---------------------------------------------------------------------------
// Kernel 1: build g table + accumulate energy into out[0] (pre-zeroed by
// memset node). Thread 0 also adds b_last. One thread per (atom, descriptor).
// ---------------------------------------------------------------------------
__global__ void table_energy_kernel(const float* __restrict__ coeffs,
                                    const float* __restrict__ w1,
                                    const float* __restrict__ b1,
                                    const float* __restrict__ w_last,
                                    const float* __restrict__ b_last,
                                    float* __restrict__ out) {
    int idx = blockIdx.x * blockDim.x + threadIdx.x;
    float e_contrib = 0.0f;
    if (idx < N_ATOMS * N_DESC) {
        int d = idx & (N_DESC - 1);
        float w = w1[d];
        float wl = w_last[d];
        float e = tanhf(fmaf(coeffs[idx], w, b1[d]));
        g_table[idx] = (1.0f - e * e) * w * wl;
        e_contrib = e * wl;
    }
    if (idx == 0) atomicAdd(out, b_last[0]);

    __shared__ float red[256 / 32];
    #pragma unroll
    for (int o = 16; o > 0; o >>= 1)
        e_contrib += __shfl_xor_sync(0xFFFFFFFFu, e_contrib, o);
    int lane = threadIdx.x & 31;
    int wid = threadIdx.x >> 5;
    if (lane == 0) red[wid] = e_contrib;
    __syncthreads();
    if (wid == 0) {
        float v = (lane < (blockDim.x >> 5)) ? red[lane] : 0.0f;
        #pragma unroll
        for (int o = 16; o > 0; o >>= 1)
            v += __shfl_xor_sync(0xFFFFFFFFu, v, o);
        if (lane == 0)
            atomicAdd(out, v * (1.0f / (float)N_ATOMS));
    }
}

// ---------------------------------------------------------------------------
// Kernel 2: pair contraction + scatter. PERSISTENT (one wave), grid-stride
// over pair-groups. Two pairs per warp-iteration: lanes 0-15 -> pair 2g,
// lanes 16-31 -> pair 2g+1. Each lane owns 4 descriptors (float4), so each
// deriv load is one warp-wide contiguous 512 B LDG.128. Derivs use __ldcs
// (evict-first) so L2 keeps g_table + the force accumulator resident.
// Next iteration's indices are prefetched before the current reduction to
// hide the idx->gather dependency chain.
// ---------------------------------------------------------------------------
__global__ void __launch_bounds__(PAIR_TPB, 8) pair_kernel(
    const float* __restrict__ derivs,          // [3, N_PAIRS, 64]
    const int* __restrict__ central,
    const int* __restrict__ neigh,
    float* __restrict__ out_f)                 // layout [3, N_ATOMS]
{
    const unsigned lane = threadIdx.x & 31;
    const unsigned half = lane >> 4;           // which pair of the group
    const unsigned l16  = lane & 15;
    const unsigned warp0 = (blockIdx.x * PAIR_TPB + threadIdx.x) >> 5;
    const unsigned wstride = (PAIR_BLOCKS * PAIR_TPB) >> 5;  // total warps
    const size_t ds = (size_t)N_PAIRS * N_DESC;

    unsigned pg = warp0;
    if (pg >= N_GROUPS) return;

    unsigned p = pg * 2 + half;
    int c  = __ldg(central + p);
    int nb = __ldg(neigh + p);

    while (true) {
        // gather g row (L2-resident), 4 descriptors per lane
        float4 g = *(const float4*)(g_table + (size_t)c * N_DESC + l16 * 4);

        const float* base = derivs + (size_t)p * N_DESC + l16 * 4;
        float4 v0 = __ldcs((const float4*)(base));
        float4 v1 = __ldcs((const float4*)(base + ds));
        float4 v2 = __ldcs((const float4*)(base + 2 * ds));

        // prefetch next group's indices (overlaps with reduction below)
        unsigned pg_next = pg + wstride;
        bool more = (pg_next < N_GROUPS);
        int c2 = 0, nb2 = 0;
        unsigned p_next = pg_next * 2 + half;
        if (more) {
            c2  = __ldg(central + p_next);
            nb2 = __ldg(neigh + p_next);
        }

        float s0 = fmaf(v0.x, g.x, fmaf(v0.y, g.y, fmaf(v0.z, g.z, v0.w * g.w)));
        float s1 = fmaf(v1.x, g.x, fmaf(v1.y, g.y, fmaf(v1.z, g.z, v1.w * g.w)));
        float s2 = fmaf(v2.x, g.x, fmaf(v2.y, g.y, fmaf(v2.z, g.z, v2.w * g.w)));

        // reduce within each 16-lane half
        #pragma unroll
        for (int o = 8; o > 0; o >>= 1) {
            s0 += __shfl_xor_sync(0xFFFFFFFFu, s0, o);
            s1 += __shfl_xor_sync(0xFFFFFFFFu, s1, o);
            s2 += __shfl_xor_sync(0xFFFFFFFFu, s2, o);
        }

        if (l16 < 3) {
            float s = (l16 == 0) ? s0 : (l16 == 1) ? s1 : s2;
            atomicAdd(out_f + (size_t)l16 * N_ATOMS + nb, -s);
        }

        if (!more) break;
        pg = pg_next;
        p  = p_next;
        c  = c2;
        nb = nb2;
    }
}

// ---------------------------------------------------------------------------
extern "C" void kernel_launch(void* const* d_in, const int* in_sizes, int n_in,
                              void* d_out, int out_size) {
    const float* coeffs   = (const float*)d_in[0];   // [1, N_ATOMS, 64]
    const float* derivs   = (const float*)d_in[1];   // [1, 3, N_PAIRS, 64]
    const float* w1       = (const float*)d_in[2];
    const float* b1       = (const float*)d_in[3];
    const float* w_last   = (const float*)d_in[4];
    const float* b_last   = (const float*)d_in[5];
    const int*   central  = (const int*)d_in[6];
    const int*   neigh    = (const int*)d_in[7];
    float* out = (float*)d_out;                      // [0]=energy, [1..30000]=forces [3,N_ATOMS]

    // 1) zero output (memset node — graph-capturable, no alloc)
    cudaMemsetAsync(out, 0, (size_t)out_size * sizeof(float));

    // 2) g table + energy (adds b_last + mean(e*w_last) into out[0])
    {
        int n = N_ATOMS * N_DESC;
        table_energy_kernel<<<(n + 255) / 256, 256>>>(coeffs, w1, b1, w_last, b_last, out);
    }

    // 3) pair contraction + scatter (persistent, one wave)
    pair_kernel<<<PAIR_BLOCKS, PAIR_TPB>>>(derivs, central, neigh, out + 1);
}